// round 11
// baseline (speedup 1.0000x reference)
#include <cuda_runtime.h>
#include <cuda_bf16.h>
#include <cuda_fp16.h>
#include <cstdint>

#define N_NODES 50000
#define N_EDGES 800000
#define IN_DIM  256
#define HC      128   // HEADS * OUT_DIM
#define HEADS   4
#define NEG_SLOPE 0.2f
#define LN_EPS  1e-5f

// Scratch (static device globals; no allocation at runtime)
__device__ __half g_hf[(size_t)N_NODES * HC];    // transformed features, fp16
__device__ float g_as[N_NODES * HEADS];          // alpha_src per node/head
__device__ float g_ad[N_NODES * HEADS];          // alpha_dst per node/head
// W pre-split (bf16 hi/lo), transposed to [n][k]
__device__ __nv_bfloat16 g_Whi[HC * IN_DIM];
__device__ __nv_bfloat16 g_Wlo[HC * IN_DIM];
// CSR-by-dst scratch
__device__ int   g_deg[N_NODES];
__device__ int   g_cur[N_NODES];
__device__ int   g_row[N_NODES + 1];
__device__ int   g_col[N_EDGES];
__device__ int   g_scan[50176];
__device__ int   g_poff[64];

// ---------------------------------------------------------------------------
// Prep (stream 0): split W into bf16 hi/lo transposed [n][k].
// ---------------------------------------------------------------------------
__global__ __launch_bounds__(256) void prep_k(const float* __restrict__ W) {
    int i = blockIdx.x * 256 + threadIdx.x;
    if (i < IN_DIM * HC) {
        int k = i >> 7, n = i & 127;
        float v = W[i];
        __nv_bfloat16 h = __float2bfloat16(v);
        float r = v - __bfloat162float(h);
        g_Whi[n * IN_DIM + k] = h;
        g_Wlo[n * IN_DIM + k] = __float2bfloat16(r);
    }
}

// CSR branch start: zero counters
__global__ __launch_bounds__(256) void zero_k() {
    int i = blockIdx.x * 256 + threadIdx.x;
    if (i < N_NODES) { g_deg[i] = 0; g_cur[i] = 0; }
}

#define MMA_BF16(D, A0, A1, A2, A3, B0, B1)                                   \
    asm volatile(                                                             \
        "mma.sync.aligned.m16n8k16.row.col.f32.bf16.bf16.f32 "                \
        "{%0,%1,%2,%3},{%4,%5,%6,%7},{%8,%9},{%0,%1,%2,%3};"                  \
        : "+f"(D[0]), "+f"(D[1]), "+f"(D[2]), "+f"(D[3])                      \
        : "r"(A0), "r"(A1), "r"(A2), "r"(A3), "r"(B0), "r"(B1))

#define CP16(dst_u32, src_ptr)                                                \
    asm volatile("cp.async.cg.shared.global [%0], [%1], 16;" ::               \
                 "r"(dst_u32), "l"(src_ptr))
#define CP_COMMIT() asm volatile("cp.async.commit_group;")
#define CP_WAIT0()  asm volatile("cp.async.wait_group 0;")

// stage layout (bytes): Xh[64][40] | Xl[64][40] | Wh[128][40] | Wl[128][40]
#define XH_OFF 0
#define XL_OFF 5120
#define WH_OFF 10240
#define WL_OFF 20480
#define STG_BYTES 30720

// ---------------------------------------------------------------------------
// K1: h = x@W via 3-term bf16-split mma, double-buffered pipeline.
// Tile M=64, N=128, K-chunk 32; 8 warps: warp tile M=16 (wid&3), N=64 (wid>>2).
// 3 CTAs/SM (smem 60KB/CTA, regs <= 85) to cut wave quantization:
// 782 CTAs / 444 slots = 1.76 waves of half-size tiles.
// ---------------------------------------------------------------------------
__global__ __launch_bounds__(256, 3) void gemm_mma_k(const float* __restrict__ x,
                                                     const float* __restrict__ att_src,
                                                     const float* __restrict__ att_dst) {
    extern __shared__ __align__(16) char sm_raw[];

    const int tid  = threadIdx.x;
    const int wid  = tid >> 5;
    const int lane = tid & 31;
    const int g    = lane >> 2;
    const int tig  = lane & 3;
    const int wm   = (wid & 3) * 16;
    const int wn   = (wid >> 2) * 64;
    const int nb   = blockIdx.x * 64;

    // per-thread fixed load coordinates: X tile 64 rows x 32 k = 512 float4
    const float* xsrc[2];
    int xoff[2];
#pragma unroll
    for (int i = 0; i < 2; i++) {
        int idx = tid + i * 256;
        int row = idx >> 3, q = idx & 7;
        int gn  = nb + row; if (gn > N_NODES - 1) gn = N_NODES - 1;
        xoff[i] = row * 40 + q * 4;
        xsrc[i] = x + (size_t)gn * IN_DIM + q * 4;
    }
    int wrow[2], wq[2];
#pragma unroll
    for (int i = 0; i < 2; i++) {
        int idx = tid + i * 256;
        wrow[i] = idx >> 2; wq[i] = idx & 3;
    }

    float d[8][4];
#pragma unroll
    for (int nt = 0; nt < 8; nt++)
#pragma unroll
        for (int c = 0; c < 4; c++) d[nt][c] = 0.f;

    float4 xs[2];

    // --- prologue: chunk 0 ---
    {
        char* st0 = sm_raw;
#pragma unroll
        for (int i = 0; i < 2; i++) {
            uint32_t dh = (uint32_t)__cvta_generic_to_shared(
                st0 + WH_OFF + (wrow[i] * 40 + wq[i] * 8) * 2);
            uint32_t dl = (uint32_t)__cvta_generic_to_shared(
                st0 + WL_OFF + (wrow[i] * 40 + wq[i] * 8) * 2);
            CP16(dh, g_Whi + (size_t)wrow[i] * IN_DIM + wq[i] * 8);
            CP16(dl, g_Wlo + (size_t)wrow[i] * IN_DIM + wq[i] * 8);
        }
        CP_COMMIT();
#pragma unroll
        for (int i = 0; i < 2; i++) xs[i] = *(const float4*)(xsrc[i]);
        __nv_bfloat16* Xh = (__nv_bfloat16*)(st0 + XH_OFF);
        __nv_bfloat16* Xl = (__nv_bfloat16*)(st0 + XL_OFF);
#pragma unroll
        for (int i = 0; i < 2; i++) {
            float4 v = xs[i];
            __nv_bfloat162 h01 = make_bfloat162(__float2bfloat16(v.x), __float2bfloat16(v.y));
            __nv_bfloat162 h23 = make_bfloat162(__float2bfloat16(v.z), __float2bfloat16(v.w));
            __nv_bfloat162 l01 = make_bfloat162(
                __float2bfloat16(v.x - __bfloat162float(h01.x)),
                __float2bfloat16(v.y - __bfloat162float(h01.y)));
            __nv_bfloat162 l23 = make_bfloat162(
                __float2bfloat16(v.z - __bfloat162float(h23.x)),
                __float2bfloat16(v.w - __bfloat162float(h23.y)));
            *(__nv_bfloat162*)&Xh[xoff[i]]     = h01;
            *(__nv_bfloat162*)&Xh[xoff[i] + 2] = h23;
            *(__nv_bfloat162*)&Xl[xoff[i]]     = l01;
            *(__nv_bfloat162*)&Xl[xoff[i] + 2] = l23;
        }
        CP_WAIT0();
        __syncthreads();
    }

    for (int c = 0; c < 8; c++) {
        const int cur = c & 1;
        const int nxt = cur ^ 1;
        char* bc = sm_raw + cur * STG_BYTES;
        char* bn = sm_raw + nxt * STG_BYTES;
        const __nv_bfloat16* Xh = (const __nv_bfloat16*)(bc + XH_OFF);
        const __nv_bfloat16* Xl = (const __nv_bfloat16*)(bc + XL_OFF);
        const __nv_bfloat16* Wh = (const __nv_bfloat16*)(bc + WH_OFF);
        const __nv_bfloat16* Wl = (const __nv_bfloat16*)(bc + WL_OFF);

        if (c < 7) {
            const int kc = (c + 1) * 32;
#pragma unroll
            for (int i = 0; i < 2; i++) {
                uint32_t dh = (uint32_t)__cvta_generic_to_shared(
                    bn + WH_OFF + (wrow[i] * 40 + wq[i] * 8) * 2);
                uint32_t dl = (uint32_t)__cvta_generic_to_shared(
                    bn + WL_OFF + (wrow[i] * 40 + wq[i] * 8) * 2);
                CP16(dh, g_Whi + (size_t)wrow[i] * IN_DIM + kc + wq[i] * 8);
                CP16(dl, g_Wlo + (size_t)wrow[i] * IN_DIM + kc + wq[i] * 8);
            }
            CP_COMMIT();
#pragma unroll
            for (int i = 0; i < 2; i++) xs[i] = *(const float4*)(xsrc[i] + kc);
        }

        // --- compute on current stage ---
#pragma unroll
        for (int ks = 0; ks < 32; ks += 16) {
            uint32_t ah[4], al[4];
            {
                int r0 = (wm + g) * 40;
                int r1 = r0 + 8 * 40;
                ah[0] = *(const uint32_t*)&Xh[r0 + ks + 2 * tig];
                ah[1] = *(const uint32_t*)&Xh[r1 + ks + 2 * tig];
                ah[2] = *(const uint32_t*)&Xh[r0 + ks + 2 * tig + 8];
                ah[3] = *(const uint32_t*)&Xh[r1 + ks + 2 * tig + 8];
                al[0] = *(const uint32_t*)&Xl[r0 + ks + 2 * tig];
                al[1] = *(const uint32_t*)&Xl[r1 + ks + 2 * tig];
                al[2] = *(const uint32_t*)&Xl[r0 + ks + 2 * tig + 8];
                al[3] = *(const uint32_t*)&Xl[r1 + ks + 2 * tig + 8];
            }
#pragma unroll
            for (int nt = 0; nt < 8; nt++) {
                int n = (wn + nt * 8 + g) * 40;
                uint32_t bh0 = *(const uint32_t*)&Wh[n + ks + 2 * tig];
                uint32_t bh1 = *(const uint32_t*)&Wh[n + ks + 2 * tig + 8];
                uint32_t bl0 = *(const uint32_t*)&Wl[n + ks + 2 * tig];
                uint32_t bl1 = *(const uint32_t*)&Wl[n + ks + 2 * tig + 8];
                MMA_BF16(d[nt], ah[0], ah[1], ah[2], ah[3], bh0, bh1);
                MMA_BF16(d[nt], ah[0], ah[1], ah[2], ah[3], bl0, bl1);
                MMA_BF16(d[nt], al[0], al[1], al[2], al[3], bh0, bh1);
            }
        }

        if (c < 7) {
            __nv_bfloat16* Xhn = (__nv_bfloat16*)(bn + XH_OFF);
            __nv_bfloat16* Xln = (__nv_bfloat16*)(bn + XL_OFF);
#pragma unroll
            for (int i = 0; i < 2; i++) {
                float4 v = xs[i];
                __nv_bfloat162 h01 = make_bfloat162(__float2bfloat16(v.x), __float2bfloat16(v.y));
                __nv_bfloat162 h23 = make_bfloat162(__float2bfloat16(v.z), __float2bfloat16(v.w));
                __nv_bfloat162 l01 = make_bfloat162(
                    __float2bfloat16(v.x - __bfloat162float(h01.x)),
                    __float2bfloat16(v.y - __bfloat162float(h01.y)));
                __nv_bfloat162 l23 = make_bfloat162(
                    __float2bfloat16(v.z - __bfloat162float(h23.x)),
                    __float2bfloat16(v.w - __bfloat162float(h23.y)));
                *(__nv_bfloat162*)&Xhn[xoff[i]]     = h01;
                *(__nv_bfloat162*)&Xhn[xoff[i] + 2] = h23;
                *(__nv_bfloat162*)&Xln[xoff[i]]     = l01;
                *(__nv_bfloat162*)&Xln[xoff[i] + 2] = l23;
            }
            CP_WAIT0();
        }
        __syncthreads();
    }

    // ---- epilogue: store h (fp16) + attention logits (fp32) ----
    // rows n0 = nb+wm+g, n1 = n0+8; cols wn + nt*8 + 2*tig (+1)
    const int head0 = wn >> 5;
    float psl[2], pdl[2], psh[2], pdh[2];
#pragma unroll
    for (int hh = 0; hh < 2; hh++) { psl[hh]=pdl[hh]=psh[hh]=pdh[hh]=0.f; }

#pragma unroll
    for (int nt = 0; nt < 8; nt++) {
        int c0 = wn + nt * 8 + 2 * tig;
        int hh = nt >> 2;
        float as0 = __ldg(att_src + c0), as1 = __ldg(att_src + c0 + 1);
        float ad0 = __ldg(att_dst + c0), ad1 = __ldg(att_dst + c0 + 1);
        psl[hh] += d[nt][0] * as0 + d[nt][1] * as1;
        pdl[hh] += d[nt][0] * ad0 + d[nt][1] * ad1;
        psh[hh] += d[nt][2] * as0 + d[nt][3] * as1;
        pdh[hh] += d[nt][2] * ad0 + d[nt][3] * ad1;
    }
#pragma unroll
    for (int hh = 0; hh < 2; hh++)
#pragma unroll
        for (int o = 1; o <= 2; o <<= 1) {
            psl[hh] += __shfl_xor_sync(0xffffffffu, psl[hh], o);
            pdl[hh] += __shfl_xor_sync(0xffffffffu, pdl[hh], o);
            psh[hh] += __shfl_xor_sync(0xffffffffu, psh[hh], o);
            pdh[hh] += __shfl_xor_sync(0xffffffffu, pdh[hh], o);
        }

    const int n0 = nb + wm + g;
    const int n1 = n0 + 8;
    if (n0 < N_NODES) {
#pragma unroll
        for (int nt = 0; nt < 8; nt++)
            *(__half2*)(g_hf + (size_t)n0 * HC + wn + nt * 8 + 2 * tig) =
                __floats2half2_rn(d[nt][0], d[nt][1]);
        if (tig == 0)
#pragma unroll
            for (int hh = 0; hh < 2; hh++) {
                g_as[n0 * HEADS + head0 + hh] = psl[hh];
                g_ad[n0 * HEADS + head0 + hh] = pdl[hh];
            }
    }
    if (n1 < N_NODES) {
#pragma unroll
        for (int nt = 0; nt < 8; nt++)
            *(__half2*)(g_hf + (size_t)n1 * HC + wn + nt * 8 + 2 * tig) =
                __floats2half2_rn(d[nt][2], d[nt][3]);
        if (tig == 0)
#pragma unroll
            for (int hh = 0; hh < 2; hh++) {
                g_as[n1 * HEADS + head0 + hh] = psh[hh];
                g_ad[n1 * HEADS + head0 + hh] = pdh[hh];
            }
    }
}

// ---------------------------------------------------------------------------
// CSR build: hist -> scan (2-level, warp-shuffle) -> fill
// ---------------------------------------------------------------------------
__global__ __launch_bounds__(256) void hist_k(const int* __restrict__ ei) {
    int e = blockIdx.x * 256 + threadIdx.x;
    if (e < N_EDGES) atomicAdd(&g_deg[__ldg(ei + N_EDGES + e)], 1);
}

__global__ __launch_bounds__(1024) void scan1_k() {
    __shared__ int wsum[32];
    int tid = threadIdx.x, lane = tid & 31, wid = tid >> 5;
    int i = blockIdx.x * 1024 + tid;
    int v = (i < N_NODES) ? g_deg[i] : 0;
    int s = v;
#pragma unroll
    for (int o = 1; o < 32; o <<= 1) {
        int t = __shfl_up_sync(0xffffffffu, s, o);
        if (lane >= o) s += t;
    }
    if (lane == 31) wsum[wid] = s;
    __syncthreads();
    if (wid == 0) {
        int t = wsum[lane];
#pragma unroll
        for (int o = 1; o < 32; o <<= 1) {
            int u = __shfl_up_sync(0xffffffffu, t, o);
            if (lane >= o) t += u;
        }
        wsum[lane] = t;
    }
    __syncthreads();
    if (wid > 0) s += wsum[wid - 1];
    g_scan[i] = s;
    if (tid == 1023) g_poff[blockIdx.x] = s;
}

__global__ __launch_bounds__(64) void scan2_k(int nblk) {
    __shared__ int s[64];
    int tid = threadIdx.x;
    s[tid] = (tid < nblk) ? g_poff[tid] : 0;
    __syncthreads();
    if (tid == 0) {
        int run = 0;
        for (int b = 0; b < nblk; b++) { int t = s[b]; s[b] = run; run += t; }
    }
    __syncthreads();
    if (tid < nblk) g_poff[tid] = s[tid];
}

__global__ __launch_bounds__(256) void scan3_k() {
    int i = blockIdx.x * 256 + threadIdx.x;
    if (i < N_NODES) g_row[i + 1] = g_scan[i] + g_poff[i >> 10];
    if (i == 0) g_row[0] = 0;
}

__global__ __launch_bounds__(256) void fill_k(const int* __restrict__ ei) {
    int e = blockIdx.x * 256 + threadIdx.x;
    if (e >= N_EDGES) return;
    int s = __ldg(ei + e);
    int d = __ldg(ei + N_EDGES + e);
    int pos = g_row[d] + atomicAdd(&g_cur[d], 1);
    g_col[pos] = s;
}

// ---------------------------------------------------------------------------
// Aggregation (fp16 gather, 4-way MLP unroll) fused with LayerNorm + ELU.
// One warp per dst node; lane owns 4 channels (one uint2 = 2 half2).
// ---------------------------------------------------------------------------
__global__ __launch_bounds__(256) void aggr_k(const float* __restrict__ bias,
                                              const float* __restrict__ gamma,
                                              const float* __restrict__ beta,
                                              float* __restrict__ out) {
    int gt   = blockIdx.x * 256 + threadIdx.x;
    int n    = gt >> 5;
    int lane = gt & 31;
    if (n >= N_NODES) return;
    int head = lane >> 3;

    float ad_n = __ldg(g_ad + n * HEADS + head);

    // self-loop initializes the accumulator
    float as_s = __ldg(g_as + n * HEADS + head);
    float z    = as_s + ad_n;
    float w    = __expf(z > 0.f ? z : NEG_SLOPE * z);
    uint2 u0i  = __ldg((const uint2*)(g_hf + (size_t)n * HC) + lane);
    float2 f01 = __half22float2(*(__half2*)&u0i.x);
    float2 f23 = __half22float2(*(__half2*)&u0i.y);
    float a0 = w * f01.x, a1 = w * f01.y, a2 = w * f23.x, a3 = w * f23.y;
    float den = w;

    const int e0 = __ldg(g_row + n), e1 = __ldg(g_row + n + 1);
    int i = e0;

    // --- unrolled by 4: batch independent loads to raise MLP ---
#pragma unroll 1
    for (; i + 4 <= e1; i += 4) {
        int s0 = __ldg(g_col + i);
        int s1 = __ldg(g_col + i + 1);
        int s2 = __ldg(g_col + i + 2);
        int s3 = __ldg(g_col + i + 3);
        uint2 u0 = __ldg((const uint2*)(g_hf + (size_t)s0 * HC) + lane);
        uint2 u1 = __ldg((const uint2*)(g_hf + (size_t)s1 * HC) + lane);
        uint2 u2 = __ldg((const uint2*)(g_hf + (size_t)s2 * HC) + lane);
        uint2 u3 = __ldg((const uint2*)(g_hf + (size_t)s3 * HC) + lane);
        float as0 = __ldg(g_as + s0 * HEADS + head);
        float as1 = __ldg(g_as + s1 * HEADS + head);
        float as2 = __ldg(g_as + s2 * HEADS + head);
        float as3 = __ldg(g_as + s3 * HEADS + head);

        float z0 = as0 + ad_n, z1 = as1 + ad_n, z2 = as2 + ad_n, z3 = as3 + ad_n;
        float w0 = __expf(z0 > 0.f ? z0 : NEG_SLOPE * z0);
        float w1 = __expf(z1 > 0.f ? z1 : NEG_SLOPE * z1);
        float w2 = __expf(z2 > 0.f ? z2 : NEG_SLOPE * z2);
        float w3 = __expf(z3 > 0.f ? z3 : NEG_SLOPE * z3);
        den += w0 + w1 + w2 + w3;

        float2 p, q2;
        p = __half22float2(*(__half2*)&u0.x); q2 = __half22float2(*(__half2*)&u0.y);
        a0 = fmaf(w0, p.x, a0); a1 = fmaf(w0, p.y, a1);
        a2 = fmaf(w0, q2.x, a2); a3 = fmaf(w0, q2.y, a3);
        p = __half22float2(*(__half2*)&u1.x); q2 = __half22float2(*(__half2*)&u1.y);
        a0 = fmaf(w1, p.x, a0); a1 = fmaf(w1, p.y, a1);
        a2 = fmaf(w1, q2.x, a2); a3 = fmaf(w1, q2.y, a3);
        p = __half22float2(*(__half2*)&u2.x); q2 = __half22float2(*(__half2*)&u2.y);
        a0 = fmaf(w2, p.x, a0); a1 = fmaf(w2, p.y, a1);
        a2 = fmaf(w2, q2.x, a2); a3 = fmaf(w2, q2.y, a3);
        p = __half22float2(*(__half2*)&u3.x); q2 = __half22float2(*(__half2*)&u3.y);
        a0 = fmaf(w3, p.x, a0); a1 = fmaf(w3, p.y, a1);
        a2 = fmaf(w3, q2.x, a2); a3 = fmaf(w3, q2.y, a3);
    }
    // --- tail ---
#pragma unroll 1
    for (; i < e1; i++) {
        int s = __ldg(g_col + i);
        uint2 u  = __ldg((const uint2*)(g_hf + (size_t)s * HC) + lane);
        float as = __ldg(g_as + s * HEADS + head);
        float zz = as + ad_n;
        float ww = __expf(zz > 0.f ? zz : NEG_SLOPE * zz);
        float2 h01 = __half22float2(*(__half2*)&u.x);
        float2 h23 = __half22float2(*(__half2*)&u.y);
        a0 = fmaf(ww, h01.x, a0);
        a1 = fmaf(ww, h01.y, a1);
        a2 = fmaf(ww, h23.x, a2);
        a3 = fmaf(ww, h23.y, a3);
        den += ww;
    }

    float inv = 1.0f / den;
    float4 b4 = __ldg((const float4*)bias + lane);
    float v0 = a0 * inv + b4.x;
    float v1 = a1 * inv + b4.y;
    float v2 = a2 * inv + b4.z;
    float v3 = a3 * inv + b4.w;

    float s = v0 + v1 + v2 + v3;
#pragma unroll
    for (int o = 16; o >= 1; o >>= 1) s += __shfl_xor_sync(0xffffffffu, s, o);
    float mean = s * (1.0f / 128.0f);

    float d0 = v0 - mean, d1 = v1 - mean, d2 = v2 - mean, d3 = v3 - mean;
    float q = d0 * d0 + d1 * d1 + d2 * d2 + d3 * d3;
#pragma unroll
    for (int o = 16; o >= 1; o >>= 1) q += __shfl_xor_sync(0xffffffffu, q, o);
    float r = rsqrtf(q * (1.0f / 128.0f) + LN_EPS);

    float4 g4  = __ldg((const float4*)gamma + lane);
    float4 be4 = __ldg((const float4*)beta + lane);
    float o0 = d0 * r * g4.x + be4.x;
    float o1 = d1 * r * g4.y + be4.y;
    float o2 = d2 * r * g4.z + be4.z;
    float o3 = d3 * r * g4.w + be4.w;
    o0 = o0 > 0.f ? o0 : (expf(o0) - 1.0f);
    o1 = o1 > 0.f ? o1 : (expf(o1) - 1.0f);
    o2 = o2 > 0.f ? o2 : (expf(o2) - 1.0f);
    o3 = o3 > 0.f ? o3 : (expf(o3) - 1.0f);

    *(float4*)(out + (size_t)n * HC + lane * 4) = make_float4(o0, o1, o2, o3);
}

// ---------------------------------------------------------------------------
// Launch: fork the capture stream so the CSR build (edge_index only) runs
// concurrently with prep+gemm (x, W only); join before aggr.
// ---------------------------------------------------------------------------
extern "C" void kernel_launch(void* const* d_in, const int* in_sizes, int n_in,
                              void* d_out, int out_size) {
    const float* x       = (const float*)d_in[0];
    const int*   ei      = (const int*)d_in[1];
    const float* W       = (const float*)d_in[2];
    const float* att_src = (const float*)d_in[3];
    const float* att_dst = (const float*)d_in[4];
    const float* bias    = (const float*)d_in[5];
    const float* gamma   = (const float*)d_in[6];
    const float* beta    = (const float*)d_in[7];
    float*       out     = (float*)d_out;

    const int NB_SCAN1  = (N_NODES + 1023) / 1024;  // 49
    const int GEMM_SMEM = 2 * STG_BYTES;            // 60 KB dynamic

    cudaFuncSetAttribute(gemm_mma_k,
                         cudaFuncAttributeMaxDynamicSharedMemorySize, GEMM_SMEM);

    cudaStream_t s2;
    cudaStreamCreateWithFlags(&s2, cudaStreamNonBlocking);
    cudaEvent_t ev_fork, ev_join;
    cudaEventCreateWithFlags(&ev_fork, cudaEventDisableTiming);
    cudaEventCreateWithFlags(&ev_join, cudaEventDisableTiming);

    cudaEventRecord(ev_fork, 0);
    cudaStreamWaitEvent(s2, ev_fork, 0);

    // --- branch A (stream 0): W prep + GEMM/logits ---
    prep_k<<<(IN_DIM * HC + 255) / 256, 256>>>(W);
    gemm_mma_k<<<(N_NODES + 63) / 64, 256, GEMM_SMEM>>>(x, att_src, att_dst);

    // --- branch B (s2): CSR build ---
    zero_k<<<(N_NODES + 255) / 256, 256, 0, s2>>>();
    hist_k<<<(N_EDGES + 255) / 256, 256, 0, s2>>>(ei);
    scan1_k<<<NB_SCAN1, 1024, 0, s2>>>();
    scan2_k<<<1, 64, 0, s2>>>(NB_SCAN1);
    scan3_k<<<(N_NODES + 255) / 256, 256, 0, s2>>>();
    fill_k<<<(N_EDGES + 255) / 256, 256, 0, s2>>>(ei);
    cudaEventRecord(ev_join, s2);

    // --- join, then aggregation + LN + ELU ---
    cudaStreamWaitEvent(0, ev_join, 0);
    aggr_k<<<(N_NODES * 32 + 255) / 256, 256>>>(bias, gamma, beta, out);
}

// round 12
// speedup vs baseline: 1.0946x; 1.0946x over previous
#include <cuda_runtime.h>
#include <cuda_bf16.h>
#include <cuda_fp16.h>
#include <cstdint>

#define N_NODES 50000
#define N_EDGES 800000
#define IN_DIM  256
#define HC      128   // HEADS * OUT_DIM
#define HEADS   4
#define NEG_SLOPE 0.2f
#define LN_EPS  1e-5f

// Scratch (static device globals; no allocation at runtime)
__device__ __half g_hf[(size_t)N_NODES * HC];    // transformed features, fp16
__device__ float g_as[N_NODES * HEADS];          // alpha_src per node/head
__device__ float g_ad[N_NODES * HEADS];          // alpha_dst per node/head
// W pre-split (bf16 hi/lo), transposed to [n][k]
__device__ __nv_bfloat16 g_Whi[HC * IN_DIM];
__device__ __nv_bfloat16 g_Wlo[HC * IN_DIM];
// CSR-by-dst scratch
__device__ int   g_deg[N_NODES];
__device__ int   g_cur[N_NODES];
__device__ int   g_row[N_NODES + 1];
__device__ int   g_col[N_EDGES];
__device__ int   g_scan[50176];
__device__ int   g_poff[64];

// ---------------------------------------------------------------------------
// Prep (stream 0): split W into bf16 hi/lo transposed [n][k].
// ---------------------------------------------------------------------------
__global__ __launch_bounds__(256) void prep_k(const float* __restrict__ W) {
    int i = blockIdx.x * 256 + threadIdx.x;
    if (i < IN_DIM * HC) {
        int k = i >> 7, n = i & 127;
        float v = W[i];
        __nv_bfloat16 h = __float2bfloat16(v);
        float r = v - __bfloat162float(h);
        g_Whi[n * IN_DIM + k] = h;
        g_Wlo[n * IN_DIM + k] = __float2bfloat16(r);
    }
}

// CSR branch start: zero counters
__global__ __launch_bounds__(256) void zero_k() {
    int i = blockIdx.x * 256 + threadIdx.x;
    if (i < N_NODES) { g_deg[i] = 0; g_cur[i] = 0; }
}

#define MMA_BF16(D, A0, A1, A2, A3, B0, B1)                                   \
    asm volatile(                                                             \
        "mma.sync.aligned.m16n8k16.row.col.f32.bf16.bf16.f32 "                \
        "{%0,%1,%2,%3},{%4,%5,%6,%7},{%8,%9},{%0,%1,%2,%3};"                  \
        : "+f"(D[0]), "+f"(D[1]), "+f"(D[2]), "+f"(D[3])                      \
        : "r"(A0), "r"(A1), "r"(A2), "r"(A3), "r"(B0), "r"(B1))

#define LDSM_X4(R0, R1, R2, R3, ADDR)                                         \
    asm volatile("ldmatrix.sync.aligned.m8n8.x4.shared.b16 {%0,%1,%2,%3}, [%4];" \
                 : "=r"(R0), "=r"(R1), "=r"(R2), "=r"(R3) : "r"(ADDR))

#define CP16(dst_u32, src_ptr)                                                \
    asm volatile("cp.async.cg.shared.global [%0], [%1], 16;" ::               \
                 "r"(dst_u32), "l"(src_ptr))
#define CP_COMMIT() asm volatile("cp.async.commit_group;")
#define CP_WAIT0()  asm volatile("cp.async.wait_group 0;")

// stage layout (bytes): Xh[128][40] | Xl | Wh[128][40] | Wl  = 4*10240
#define STG_BYTES 40960
#define XH_OFF 0
#define XL_OFF 10240
#define WH_OFF 20480
#define WL_OFF 30720

// ---------------------------------------------------------------------------
// K1: h = x@W via 3-term bf16-split mma, double-buffered pipeline.
// Tile M=128, N=128, K-chunk 32; warp tile M=32 (2 m16), N=64 (8 n8).
// Fragments loaded with ldmatrix.x4 (conflict-free: row stride 80B).
// ---------------------------------------------------------------------------
__global__ __launch_bounds__(256, 2) void gemm_mma_k(const float* __restrict__ x,
                                                     const float* __restrict__ att_src,
                                                     const float* __restrict__ att_dst) {
    extern __shared__ __align__(16) char sm_raw[];

    const int tid  = threadIdx.x;
    const int wid  = tid >> 5;
    const int lane = tid & 31;
    const int g    = lane >> 2;
    const int tig  = lane & 3;
    const int wm   = (wid & 3) * 32;
    const int wn   = (wid >> 2) * 64;
    const int nb   = blockIdx.x * 128;

    const uint32_t smem_u32 = (uint32_t)__cvta_generic_to_shared(sm_raw);

    // ldmatrix per-lane byte offsets within a stage (excluding ks*2):
    // A (x4 = m16xk16 for one mt): m0=(rows0-7,k0-7) m1=(rows8-15,k0-7)
    //                              m2=(rows0-7,k8-15) m3=(rows8-15,k8-15)
    // lanes 0-7->m0, 8-15->m1, 16-23->m2, 24-31->m3
    int a_off[2];
#pragma unroll
    for (int mt = 0; mt < 2; mt++)
        a_off[mt] = (((wm + mt * 16 + (lane & 7) + ((lane >> 3) & 1) * 8) * 40)
                     + ((lane >> 4) & 1) * 8) * 2;
    // B (x4 covers n-tiles 2p,2p+1): m0=(nt rows,k0-7) m1=(nt,k8-15)
    //                                m2=(nt+1,k0-7) m3=(nt+1,k8-15)
    // lanes 0-7->m0, 8-15->m1 (k+8), 16-23->m2 (rows+8), 24-31->m3 (both)
    int b_off[4];
#pragma unroll
    for (int p = 0; p < 4; p++)
        b_off[p] = (((wn + p * 16 + (lane & 7) + ((lane >> 4) & 1) * 8) * 40)
                    + ((lane >> 3) & 1) * 8) * 2;

    // per-thread fixed load coordinates
    const float* xsrc[4];
    int xrow[4], xq[4];
#pragma unroll
    for (int i = 0; i < 4; i++) {
        int idx = tid + i * 256;
        int row = idx >> 3, q = idx & 7;
        int gn  = nb + row; if (gn > N_NODES - 1) gn = N_NODES - 1;
        xrow[i] = row; xq[i] = q;
        xsrc[i] = x + (size_t)gn * IN_DIM + q * 4;
    }
    int wrow[2], wq[2];
#pragma unroll
    for (int i = 0; i < 2; i++) {
        int idx = tid + i * 256;
        wrow[i] = idx >> 2; wq[i] = idx & 3;
    }

    float d[2][8][4];
#pragma unroll
    for (int mt = 0; mt < 2; mt++)
#pragma unroll
        for (int nt = 0; nt < 8; nt++)
#pragma unroll
            for (int c = 0; c < 4; c++) d[mt][nt][c] = 0.f;

    float4 xs[4];

    // --- prologue: chunk 0 ---
    {
        char* st0 = sm_raw;
#pragma unroll
        for (int i = 0; i < 2; i++) {
            uint32_t dh = smem_u32 + WH_OFF + (wrow[i] * 40 + wq[i] * 8) * 2;
            uint32_t dl = smem_u32 + WL_OFF + (wrow[i] * 40 + wq[i] * 8) * 2;
            CP16(dh, g_Whi + (size_t)wrow[i] * IN_DIM + wq[i] * 8);
            CP16(dl, g_Wlo + (size_t)wrow[i] * IN_DIM + wq[i] * 8);
        }
        CP_COMMIT();
#pragma unroll
        for (int i = 0; i < 4; i++) xs[i] = *(const float4*)(xsrc[i]);
        __nv_bfloat16* Xh = (__nv_bfloat16*)(st0 + XH_OFF);
        __nv_bfloat16* Xl = (__nv_bfloat16*)(st0 + XL_OFF);
#pragma unroll
        for (int i = 0; i < 4; i++) {
            float4 v = xs[i];
            __nv_bfloat162 h01 = make_bfloat162(__float2bfloat16(v.x), __float2bfloat16(v.y));
            __nv_bfloat162 h23 = make_bfloat162(__float2bfloat16(v.z), __float2bfloat16(v.w));
            __nv_bfloat162 l01 = make_bfloat162(
                __float2bfloat16(v.x - __bfloat162float(h01.x)),
                __float2bfloat16(v.y - __bfloat162float(h01.y)));
            __nv_bfloat162 l23 = make_bfloat162(
                __float2bfloat16(v.z - __bfloat162float(h23.x)),
                __float2bfloat16(v.w - __bfloat162float(h23.y)));
            int o = xrow[i] * 40 + xq[i] * 4;
            *(__nv_bfloat162*)&Xh[o]     = h01;
            *(__nv_bfloat162*)&Xh[o + 2] = h23;
            *(__nv_bfloat162*)&Xl[o]     = l01;
            *(__nv_bfloat162*)&Xl[o + 2] = l23;
        }
        CP_WAIT0();
        __syncthreads();
    }

    for (int c = 0; c < 8; c++) {
        const int cur = c & 1;
        const int nxt = cur ^ 1;
        char* bn = sm_raw + nxt * STG_BYTES;
        const uint32_t base = smem_u32 + cur * STG_BYTES;

        if (c < 7) {
            const int kc = (c + 1) * 32;
#pragma unroll
            for (int i = 0; i < 2; i++) {
                uint32_t dh = smem_u32 + nxt * STG_BYTES + WH_OFF + (wrow[i] * 40 + wq[i] * 8) * 2;
                uint32_t dl = smem_u32 + nxt * STG_BYTES + WL_OFF + (wrow[i] * 40 + wq[i] * 8) * 2;
                CP16(dh, g_Whi + (size_t)wrow[i] * IN_DIM + kc + wq[i] * 8);
                CP16(dl, g_Wlo + (size_t)wrow[i] * IN_DIM + kc + wq[i] * 8);
            }
            CP_COMMIT();
#pragma unroll
            for (int i = 0; i < 4; i++) xs[i] = *(const float4*)(xsrc[i] + kc);
        }

        // --- compute on current stage (ldmatrix fragment loads) ---
#pragma unroll
        for (int ks = 0; ks < 32; ks += 16) {
            uint32_t ah[2][4], al[2][4];
#pragma unroll
            for (int mt = 0; mt < 2; mt++) {
                LDSM_X4(ah[mt][0], ah[mt][1], ah[mt][2], ah[mt][3],
                        base + XH_OFF + a_off[mt] + ks * 2);
                LDSM_X4(al[mt][0], al[mt][1], al[mt][2], al[mt][3],
                        base + XL_OFF + a_off[mt] + ks * 2);
            }
#pragma unroll
            for (int p = 0; p < 4; p++) {
                uint32_t bh[4], bl[4];
                LDSM_X4(bh[0], bh[1], bh[2], bh[3],
                        base + WH_OFF + b_off[p] + ks * 2);
                LDSM_X4(bl[0], bl[1], bl[2], bl[3],
                        base + WL_OFF + b_off[p] + ks * 2);
#pragma unroll
                for (int j = 0; j < 2; j++) {
                    int nt = 2 * p + j;
                    uint32_t bh0 = bh[2 * j], bh1 = bh[2 * j + 1];
                    uint32_t bl0 = bl[2 * j], bl1 = bl[2 * j + 1];
#pragma unroll
                    for (int mt = 0; mt < 2; mt++) {
                        MMA_BF16(d[mt][nt], ah[mt][0], ah[mt][1], ah[mt][2], ah[mt][3], bh0, bh1);
                        MMA_BF16(d[mt][nt], ah[mt][0], ah[mt][1], ah[mt][2], ah[mt][3], bl0, bl1);
                        MMA_BF16(d[mt][nt], al[mt][0], al[mt][1], al[mt][2], al[mt][3], bh0, bh1);
                    }
                }
            }
        }

        if (c < 7) {
            __nv_bfloat16* Xhn = (__nv_bfloat16*)(bn + XH_OFF);
            __nv_bfloat16* Xln = (__nv_bfloat16*)(bn + XL_OFF);
#pragma unroll
            for (int i = 0; i < 4; i++) {
                float4 v = xs[i];
                __nv_bfloat162 h01 = make_bfloat162(__float2bfloat16(v.x), __float2bfloat16(v.y));
                __nv_bfloat162 h23 = make_bfloat162(__float2bfloat16(v.z), __float2bfloat16(v.w));
                __nv_bfloat162 l01 = make_bfloat162(
                    __float2bfloat16(v.x - __bfloat162float(h01.x)),
                    __float2bfloat16(v.y - __bfloat162float(h01.y)));
                __nv_bfloat162 l23 = make_bfloat162(
                    __float2bfloat16(v.z - __bfloat162float(h23.x)),
                    __float2bfloat16(v.w - __bfloat162float(h23.y)));
                int o = xrow[i] * 40 + xq[i] * 4;
                *(__nv_bfloat162*)&Xhn[o]     = h01;
                *(__nv_bfloat162*)&Xhn[o + 2] = h23;
                *(__nv_bfloat162*)&Xln[o]     = l01;
                *(__nv_bfloat162*)&Xln[o + 2] = l23;
            }
            CP_WAIT0();
        }
        __syncthreads();
    }

    // ---- epilogue: store h (fp16) + attention logits (fp32) ----
    const int head0 = wn >> 5;
    float psl[2][2], pdl[2][2], psh[2][2], pdh[2][2];
#pragma unroll
    for (int mt = 0; mt < 2; mt++)
#pragma unroll
        for (int hh = 0; hh < 2; hh++) { psl[mt][hh]=pdl[mt][hh]=psh[mt][hh]=pdh[mt][hh]=0.f; }

#pragma unroll
    for (int nt = 0; nt < 8; nt++) {
        int c0 = wn + nt * 8 + 2 * tig;
        int hh = nt >> 2;
        float as0 = __ldg(att_src + c0), as1 = __ldg(att_src + c0 + 1);
        float ad0 = __ldg(att_dst + c0), ad1 = __ldg(att_dst + c0 + 1);
#pragma unroll
        for (int mt = 0; mt < 2; mt++) {
            psl[mt][hh] += d[mt][nt][0] * as0 + d[mt][nt][1] * as1;
            pdl[mt][hh] += d[mt][nt][0] * ad0 + d[mt][nt][1] * ad1;
            psh[mt][hh] += d[mt][nt][2] * as0 + d[mt][nt][3] * as1;
            pdh[mt][hh] += d[mt][nt][2] * ad0 + d[mt][nt][3] * ad1;
        }
    }
#pragma unroll
    for (int mt = 0; mt < 2; mt++)
#pragma unroll
        for (int hh = 0; hh < 2; hh++)
#pragma unroll
            for (int o = 1; o <= 2; o <<= 1) {
                psl[mt][hh] += __shfl_xor_sync(0xffffffffu, psl[mt][hh], o);
                pdl[mt][hh] += __shfl_xor_sync(0xffffffffu, pdl[mt][hh], o);
                psh[mt][hh] += __shfl_xor_sync(0xffffffffu, psh[mt][hh], o);
                pdh[mt][hh] += __shfl_xor_sync(0xffffffffu, pdh[mt][hh], o);
            }

#pragma unroll
    for (int mt = 0; mt < 2; mt++) {
        int n0 = nb + wm + mt * 16 + g;
        int n1 = n0 + 8;
        if (n0 < N_NODES) {
#pragma unroll
            for (int nt = 0; nt < 8; nt++)
                *(__half2*)(g_hf + (size_t)n0 * HC + wn + nt * 8 + 2 * tig) =
                    __floats2half2_rn(d[mt][nt][0], d[mt][nt][1]);
            if (tig == 0)
#pragma unroll
                for (int hh = 0; hh < 2; hh++) {
                    g_as[n0 * HEADS + head0 + hh] = psl[mt][hh];
                    g_ad[n0 * HEADS + head0 + hh] = pdl[mt][hh];
                }
        }
        if (n1 < N_NODES) {
#pragma unroll
            for (int nt = 0; nt < 8; nt++)
                *(__half2*)(g_hf + (size_t)n1 * HC + wn + nt * 8 + 2 * tig) =
                    __floats2half2_rn(d[mt][nt][2], d[mt][nt][3]);
            if (tig == 0)
#pragma unroll
                for (int hh = 0; hh < 2; hh++) {
                    g_as[n1 * HEADS + head0 + hh] = psh[mt][hh];
                    g_ad[n1 * HEADS + head0 + hh] = pdh[mt][hh];
                }
        }
    }
}

// ---------------------------------------------------------------------------
// CSR build: hist -> scan (2-level, warp-shuffle) -> fill
// ---------------------------------------------------------------------------
__global__ __launch_bounds__(256) void hist_k(const int* __restrict__ ei) {
    int e = blockIdx.x * 256 + threadIdx.x;
    if (e < N_EDGES) atomicAdd(&g_deg[__ldg(ei + N_EDGES + e)], 1);
}

__global__ __launch_bounds__(1024) void scan1_k() {
    __shared__ int wsum[32];
    int tid = threadIdx.x, lane = tid & 31, wid = tid >> 5;
    int i = blockIdx.x * 1024 + tid;
    int v = (i < N_NODES) ? g_deg[i] : 0;
    int s = v;
#pragma unroll
    for (int o = 1; o < 32; o <<= 1) {
        int t = __shfl_up_sync(0xffffffffu, s, o);
        if (lane >= o) s += t;
    }
    if (lane == 31) wsum[wid] = s;
    __syncthreads();
    if (wid == 0) {
        int t = wsum[lane];
#pragma unroll
        for (int o = 1; o < 32; o <<= 1) {
            int u = __shfl_up_sync(0xffffffffu, t, o);
            if (lane >= o) t += u;
        }
        wsum[lane] = t;
    }
    __syncthreads();
    if (wid > 0) s += wsum[wid - 1];
    g_scan[i] = s;
    if (tid == 1023) g_poff[blockIdx.x] = s;
}

__global__ __launch_bounds__(64) void scan2_k(int nblk) {
    __shared__ int s[64];
    int tid = threadIdx.x;
    s[tid] = (tid < nblk) ? g_poff[tid] : 0;
    __syncthreads();
    if (tid == 0) {
        int run = 0;
        for (int b = 0; b < nblk; b++) { int t = s[b]; s[b] = run; run += t; }
    }
    __syncthreads();
    if (tid < nblk) g_poff[tid] = s[tid];
}

__global__ __launch_bounds__(256) void scan3_k() {
    int i = blockIdx.x * 256 + threadIdx.x;
    if (i < N_NODES) g_row[i + 1] = g_scan[i] + g_poff[i >> 10];
    if (i == 0) g_row[0] = 0;
}

__global__ __launch_bounds__(256) void fill_k(const int* __restrict__ ei) {
    int e = blockIdx.x * 256 + threadIdx.x;
    if (e >= N_EDGES) return;
    int s = __ldg(ei + e);
    int d = __ldg(ei + N_EDGES + e);
    int pos = g_row[d] + atomicAdd(&g_cur[d], 1);
    g_col[pos] = s;
}

// ---------------------------------------------------------------------------
// Aggregation (fp16 gather, 4-way MLP unroll) fused with LayerNorm + ELU.
// One warp per dst node; lane owns 4 channels (one uint2 = 2 half2).
// ---------------------------------------------------------------------------
__global__ __launch_bounds__(256) void aggr_k(const float* __restrict__ bias,
                                              const float* __restrict__ gamma,
                                              const float* __restrict__ beta,
                                              float* __restrict__ out) {
    int gt   = blockIdx.x * 256 + threadIdx.x;
    int n    = gt >> 5;
    int lane = gt & 31;
    if (n >= N_NODES) return;
    int head = lane >> 3;

    float ad_n = __ldg(g_ad + n * HEADS + head);

    // self-loop initializes the accumulator
    float as_s = __ldg(g_as + n * HEADS + head);
    float z    = as_s + ad_n;
    float w    = __expf(z > 0.f ? z : NEG_SLOPE * z);
    uint2 u0i  = __ldg((const uint2*)(g_hf + (size_t)n * HC) + lane);
    float2 f01 = __half22float2(*(__half2*)&u0i.x);
    float2 f23 = __half22float2(*(__half2*)&u0i.y);
    float a0 = w * f01.x, a1 = w * f01.y, a2 = w * f23.x, a3 = w * f23.y;
    float den = w;

    const int e0 = __ldg(g_row + n), e1 = __ldg(g_row + n + 1);
    int i = e0;

    // --- unrolled by 4: batch independent loads to raise MLP ---
#pragma unroll 1
    for (; i + 4 <= e1; i += 4) {
        int s0 = __ldg(g_col + i);
        int s1 = __ldg(g_col + i + 1);
        int s2 = __ldg(g_col + i + 2);
        int s3 = __ldg(g_col + i + 3);
        uint2 u0 = __ldg((const uint2*)(g_hf + (size_t)s0 * HC) + lane);
        uint2 u1 = __ldg((const uint2*)(g_hf + (size_t)s1 * HC) + lane);
        uint2 u2 = __ldg((const uint2*)(g_hf + (size_t)s2 * HC) + lane);
        uint2 u3 = __ldg((const uint2*)(g_hf + (size_t)s3 * HC) + lane);
        float as0 = __ldg(g_as + s0 * HEADS + head);
        float as1 = __ldg(g_as + s1 * HEADS + head);
        float as2 = __ldg(g_as + s2 * HEADS + head);
        float as3 = __ldg(g_as + s3 * HEADS + head);

        float z0 = as0 + ad_n, z1 = as1 + ad_n, z2 = as2 + ad_n, z3 = as3 + ad_n;
        float w0 = __expf(z0 > 0.f ? z0 : NEG_SLOPE * z0);
        float w1 = __expf(z1 > 0.f ? z1 : NEG_SLOPE * z1);
        float w2 = __expf(z2 > 0.f ? z2 : NEG_SLOPE * z2);
        float w3 = __expf(z3 > 0.f ? z3 : NEG_SLOPE * z3);
        den += w0 + w1 + w2 + w3;

        float2 p, q2;
        p = __half22float2(*(__half2*)&u0.x); q2 = __half22float2(*(__half2*)&u0.y);
        a0 = fmaf(w0, p.x, a0); a1 = fmaf(w0, p.y, a1);
        a2 = fmaf(w0, q2.x, a2); a3 = fmaf(w0, q2.y, a3);
        p = __half22float2(*(__half2*)&u1.x); q2 = __half22float2(*(__half2*)&u1.y);
        a0 = fmaf(w1, p.x, a0); a1 = fmaf(w1, p.y, a1);
        a2 = fmaf(w1, q2.x, a2); a3 = fmaf(w1, q2.y, a3);
        p = __half22float2(*(__half2*)&u2.x); q2 = __half22float2(*(__half2*)&u2.y);
        a0 = fmaf(w2, p.x, a0); a1 = fmaf(w2, p.y, a1);
        a2 = fmaf(w2, q2.x, a2); a3 = fmaf(w2, q2.y, a3);
        p = __half22float2(*(__half2*)&u3.x); q2 = __half22float2(*(__half2*)&u3.y);
        a0 = fmaf(w3, p.x, a0); a1 = fmaf(w3, p.y, a1);
        a2 = fmaf(w3, q2.x, a2); a3 = fmaf(w3, q2.y, a3);
    }
    // --- tail ---
#pragma unroll 1
    for (; i < e1; i++) {
        int s = __ldg(g_col + i);
        uint2 u  = __ldg((const uint2*)(g_hf + (size_t)s * HC) + lane);
        float as = __ldg(g_as + s * HEADS + head);
        float zz = as + ad_n;
        float ww = __expf(zz > 0.f ? zz : NEG_SLOPE * zz);
        float2 h01 = __half22float2(*(__half2*)&u.x);
        float2 h23 = __half22float2(*(__half2*)&u.y);
        a0 = fmaf(ww, h01.x, a0);
        a1 = fmaf(ww, h01.y, a1);
        a2 = fmaf(ww, h23.x, a2);
        a3 = fmaf(ww, h23.y, a3);
        den += ww;
    }

    float inv = 1.0f / den;
    float4 b4 = __ldg((const float4*)bias + lane);
    float v0 = a0 * inv + b4.x;
    float v1 = a1 * inv + b4.y;
    float v2 = a2 * inv + b4.z;
    float v3 = a3 * inv + b4.w;

    float s = v0 + v1 + v2 + v3;
#pragma unroll
    for (int o = 16; o >= 1; o >>= 1) s += __shfl_xor_sync(0xffffffffu, s, o);
    float mean = s * (1.0f / 128.0f);

    float d0 = v0 - mean, d1 = v1 - mean, d2 = v2 - mean, d3 = v3 - mean;
    float q = d0 * d0 + d1 * d1 + d2 * d2 + d3 * d3;
#pragma unroll
    for (int o = 16; o >= 1; o >>= 1) q += __shfl_xor_sync(0xffffffffu, q, o);
    float r = rsqrtf(q * (1.0f / 128.0f) + LN_EPS);

    float4 g4  = __ldg((const float4*)gamma + lane);
    float4 be4 = __ldg((const float4*)beta + lane);
    float o0 = d0 * r * g4.x + be4.x;
    float o1 = d1 * r * g4.y + be4.y;
    float o2 = d2 * r * g4.z + be4.z;
    float o3 = d3 * r * g4.w + be4.w;
    o0 = o0 > 0.f ? o0 : (expf(o0) - 1.0f);
    o1 = o1 > 0.f ? o1 : (expf(o1) - 1.0f);
    o2 = o2 > 0.f ? o2 : (expf(o2) - 1.0f);
    o3 = o3 > 0.f ? o3 : (expf(o3) - 1.0f);

    *(float4*)(out + (size_t)n * HC + lane * 4) = make_float4(o0, o1, o2, o3);
}

// ---------------------------------------------------------------------------
// Launch: fork the capture stream so the CSR build (edge_index only) runs
// concurrently with prep+gemm (x, W only); join before aggr.
// ---------------------------------------------------------------------------
extern "C" void kernel_launch(void* const* d_in, const int* in_sizes, int n_in,
                              void* d_out, int out_size) {
    const float* x       = (const float*)d_in[0];
    const int*   ei      = (const int*)d_in[1];
    const float* W       = (const float*)d_in[2];
    const float* att_src = (const float*)d_in[3];
    const float* att_dst = (const float*)d_in[4];
    const float* bias    = (const float*)d_in[5];
    const float* gamma   = (const float*)d_in[6];
    const float* beta    = (const float*)d_in[7];
    float*       out     = (float*)d_out;

    const int NB_SCAN1  = (N_NODES + 1023) / 1024;  // 49
    const int GEMM_SMEM = 2 * STG_BYTES;            // 80 KB dynamic

    cudaFuncSetAttribute(gemm_mma_k,
                         cudaFuncAttributeMaxDynamicSharedMemorySize, GEMM_SMEM);

    cudaStream_t s2;
    cudaStreamCreateWithFlags(&s2, cudaStreamNonBlocking);
    cudaEvent_t ev_fork, ev_join;
    cudaEventCreateWithFlags(&ev_fork, cudaEventDisableTiming);
    cudaEventCreateWithFlags(&ev_join, cudaEventDisableTiming);

    cudaEventRecord(ev_fork, 0);
    cudaStreamWaitEvent(s2, ev_fork, 0);

    // --- branch A (stream 0): W prep + GEMM/logits ---
    prep_k<<<(IN_DIM * HC + 255) / 256, 256>>>(W);
    gemm_mma_k<<<(N_NODES + 127) / 128, 256, GEMM_SMEM>>>(x, att_src, att_dst);

    // --- branch B (s2): CSR build ---
    zero_k<<<(N_NODES + 255) / 256, 256, 0, s2>>>();
    hist_k<<<(N_EDGES + 255) / 256, 256, 0, s2>>>(ei);
    scan1_k<<<NB_SCAN1, 1024, 0, s2>>>();
    scan2_k<<<1, 64, 0, s2>>>(NB_SCAN1);
    scan3_k<<<(N_NODES + 255) / 256, 256, 0, s2>>>();
    fill_k<<<(N_EDGES + 255) / 256, 256, 0, s2>>>(ei);
    cudaEventRecord(ev_join, s2);

    // --- join, then aggregation + LN + ELU ---
    cudaStreamWaitEvent(0, ev_join, 0);
    aggr_k<<<(N_NODES * 32 + 255) / 256, 256>>>(bias, gamma, beta, out);
}

// round 14
// speedup vs baseline: 1.0984x; 1.0034x over previous
#include <cuda_runtime.h>
#include <cuda_bf16.h>
#include <cuda_fp16.h>
#include <cstdint>

#define N_NODES 50000
#define N_EDGES 800000
#define IN_DIM  256
#define HC      128   // HEADS * OUT_DIM
#define HEADS   4
#define NEG_SLOPE 0.2f
#define LN_EPS  1e-5f

// Scratch (static device globals; no allocation at runtime)
__device__ __half g_hf[(size_t)N_NODES * HC];    // transformed features, fp16
__device__ float g_as[N_NODES * HEADS];          // alpha_src per node/head
__device__ float g_ad[N_NODES * HEADS];          // alpha_dst per node/head
// W pre-split (bf16 hi/lo), transposed to [n][k]
__device__ __nv_bfloat16 g_Whi[HC * IN_DIM];
__device__ __nv_bfloat16 g_Wlo[HC * IN_DIM];
// CSR-by-dst scratch
__device__ int   g_deg[N_NODES];
__device__ int   g_cur[N_NODES];
__device__ int   g_row[N_NODES + 1];
__device__ int   g_col[N_EDGES];
__device__ int   g_scan[50176];
__device__ int   g_poff[64];

// ---------------------------------------------------------------------------
// Prep (stream 0): split W into bf16 hi/lo transposed [n][k].
// ---------------------------------------------------------------------------
__global__ __launch_bounds__(256) void prep_k(const float* __restrict__ W) {
    int i = blockIdx.x * 256 + threadIdx.x;
    if (i < IN_DIM * HC) {
        int k = i >> 7, n = i & 127;
        float v = W[i];
        __nv_bfloat16 h = __float2bfloat16(v);
        float r = v - __bfloat162float(h);
        g_Whi[n * IN_DIM + k] = h;
        g_Wlo[n * IN_DIM + k] = __float2bfloat16(r);
    }
}

// CSR branch start: zero counters
__global__ __launch_bounds__(256) void zero_k() {
    int i = blockIdx.x * 256 + threadIdx.x;
    if (i < N_NODES) { g_deg[i] = 0; g_cur[i] = 0; }
}

#define MMA_BF16(D, A0, A1, A2, A3, B0, B1)                                   \
    asm volatile(                                                             \
        "mma.sync.aligned.m16n8k16.row.col.f32.bf16.bf16.f32 "                \
        "{%0,%1,%2,%3},{%4,%5,%6,%7},{%8,%9},{%0,%1,%2,%3};"                  \
        : "+f"(D[0]), "+f"(D[1]), "+f"(D[2]), "+f"(D[3])                      \
        : "r"(A0), "r"(A1), "r"(A2), "r"(A3), "r"(B0), "r"(B1))

#define LDSM_X4(R0, R1, R2, R3, ADDR)                                         \
    asm volatile("ldmatrix.sync.aligned.m8n8.x4.shared.b16 {%0,%1,%2,%3}, [%4];" \
                 : "=r"(R0), "=r"(R1), "=r"(R2), "=r"(R3) : "r"(ADDR))

#define CP16(dst_u32, src_ptr)                                                \
    asm volatile("cp.async.cg.shared.global [%0], [%1], 16;" ::               \
                 "r"(dst_u32), "l"(src_ptr))
#define CP_COMMIT() asm volatile("cp.async.commit_group;")
#define CP_WAIT0()  asm volatile("cp.async.wait_group 0;")

// stage layout (bytes): Xh[128][40] | Xl | Wh[128][40] | Wl  = 4*10240
#define STG_BYTES 40960
#define XH_OFF 0
#define XL_OFF 10240
#define WH_OFF 20480
#define WL_OFF 30720

// ---------------------------------------------------------------------------
// K1: h = x@W via 3-term bf16-split mma, double-buffered pipeline.
// Tile M=128, N=128, K-chunk 32; warp tile M=32 (2 m16), N=64 (8 n8).
// Fragments loaded with ldmatrix.x4 (conflict-free: row stride 80B).
// ---------------------------------------------------------------------------
__global__ __launch_bounds__(256, 2) void gemm_mma_k(const float* __restrict__ x,
                                                     const float* __restrict__ att_src,
                                                     const float* __restrict__ att_dst) {
    extern __shared__ __align__(16) char sm_raw[];

    const int tid  = threadIdx.x;
    const int wid  = tid >> 5;
    const int lane = tid & 31;
    const int g    = lane >> 2;
    const int tig  = lane & 3;
    const int wm   = (wid & 3) * 32;
    const int wn   = (wid >> 2) * 64;
    const int nb   = blockIdx.x * 128;

    const uint32_t smem_u32 = (uint32_t)__cvta_generic_to_shared(sm_raw);

    int a_off[2];
#pragma unroll
    for (int mt = 0; mt < 2; mt++)
        a_off[mt] = (((wm + mt * 16 + (lane & 7) + ((lane >> 3) & 1) * 8) * 40)
                     + ((lane >> 4) & 1) * 8) * 2;
    int b_off[4];
#pragma unroll
    for (int p = 0; p < 4; p++)
        b_off[p] = (((wn + p * 16 + (lane & 7) + ((lane >> 4) & 1) * 8) * 40)
                    + ((lane >> 3) & 1) * 8) * 2;

    const float* xsrc[4];
    int xrow[4], xq[4];
#pragma unroll
    for (int i = 0; i < 4; i++) {
        int idx = tid + i * 256;
        int row = idx >> 3, q = idx & 7;
        int gn  = nb + row; if (gn > N_NODES - 1) gn = N_NODES - 1;
        xrow[i] = row; xq[i] = q;
        xsrc[i] = x + (size_t)gn * IN_DIM + q * 4;
    }
    int wrow[2], wq[2];
#pragma unroll
    for (int i = 0; i < 2; i++) {
        int idx = tid + i * 256;
        wrow[i] = idx >> 2; wq[i] = idx & 3;
    }

    float d[2][8][4];
#pragma unroll
    for (int mt = 0; mt < 2; mt++)
#pragma unroll
        for (int nt = 0; nt < 8; nt++)
#pragma unroll
            for (int c = 0; c < 4; c++) d[mt][nt][c] = 0.f;

    float4 xs[4];

    // --- prologue: chunk 0 ---
    {
        char* st0 = sm_raw;
#pragma unroll
        for (int i = 0; i < 2; i++) {
            uint32_t dh = smem_u32 + WH_OFF + (wrow[i] * 40 + wq[i] * 8) * 2;
            uint32_t dl = smem_u32 + WL_OFF + (wrow[i] * 40 + wq[i] * 8) * 2;
            CP16(dh, g_Whi + (size_t)wrow[i] * IN_DIM + wq[i] * 8);
            CP16(dl, g_Wlo + (size_t)wrow[i] * IN_DIM + wq[i] * 8);
        }
        CP_COMMIT();
#pragma unroll
        for (int i = 0; i < 4; i++) xs[i] = *(const float4*)(xsrc[i]);
        __nv_bfloat16* Xh = (__nv_bfloat16*)(st0 + XH_OFF);
        __nv_bfloat16* Xl = (__nv_bfloat16*)(st0 + XL_OFF);
#pragma unroll
        for (int i = 0; i < 4; i++) {
            float4 v = xs[i];
            __nv_bfloat162 h01 = make_bfloat162(__float2bfloat16(v.x), __float2bfloat16(v.y));
            __nv_bfloat162 h23 = make_bfloat162(__float2bfloat16(v.z), __float2bfloat16(v.w));
            __nv_bfloat162 l01 = make_bfloat162(
                __float2bfloat16(v.x - __bfloat162float(h01.x)),
                __float2bfloat16(v.y - __bfloat162float(h01.y)));
            __nv_bfloat162 l23 = make_bfloat162(
                __float2bfloat16(v.z - __bfloat162float(h23.x)),
                __float2bfloat16(v.w - __bfloat162float(h23.y)));
            int o = xrow[i] * 40 + xq[i] * 4;
            *(__nv_bfloat162*)&Xh[o]     = h01;
            *(__nv_bfloat162*)&Xh[o + 2] = h23;
            *(__nv_bfloat162*)&Xl[o]     = l01;
            *(__nv_bfloat162*)&Xl[o + 2] = l23;
        }
        CP_WAIT0();
        __syncthreads();
    }

    for (int c = 0; c < 8; c++) {
        const int cur = c & 1;
        const int nxt = cur ^ 1;
        char* bn = sm_raw + nxt * STG_BYTES;
        const uint32_t base = smem_u32 + cur * STG_BYTES;

        if (c < 7) {
            const int kc = (c + 1) * 32;
#pragma unroll
            for (int i = 0; i < 2; i++) {
                uint32_t dh = smem_u32 + nxt * STG_BYTES + WH_OFF + (wrow[i] * 40 + wq[i] * 8) * 2;
                uint32_t dl = smem_u32 + nxt * STG_BYTES + WL_OFF + (wrow[i] * 40 + wq[i] * 8) * 2;
                CP16(dh, g_Whi + (size_t)wrow[i] * IN_DIM + kc + wq[i] * 8);
                CP16(dl, g_Wlo + (size_t)wrow[i] * IN_DIM + kc + wq[i] * 8);
            }
            CP_COMMIT();
#pragma unroll
            for (int i = 0; i < 4; i++) xs[i] = *(const float4*)(xsrc[i] + kc);
        }

        // --- compute on current stage (ldmatrix fragment loads) ---
#pragma unroll
        for (int ks = 0; ks < 32; ks += 16) {
            uint32_t ah[2][4], al[2][4];
#pragma unroll
            for (int mt = 0; mt < 2; mt++) {
                LDSM_X4(ah[mt][0], ah[mt][1], ah[mt][2], ah[mt][3],
                        base + XH_OFF + a_off[mt] + ks * 2);
                LDSM_X4(al[mt][0], al[mt][1], al[mt][2], al[mt][3],
                        base + XL_OFF + a_off[mt] + ks * 2);
            }
#pragma unroll
            for (int p = 0; p < 4; p++) {
                uint32_t bh[4], bl[4];
                LDSM_X4(bh[0], bh[1], bh[2], bh[3],
                        base + WH_OFF + b_off[p] + ks * 2);
                LDSM_X4(bl[0], bl[1], bl[2], bl[3],
                        base + WL_OFF + b_off[p] + ks * 2);
#pragma unroll
                for (int j = 0; j < 2; j++) {
                    int nt = 2 * p + j;
                    uint32_t bh0 = bh[2 * j], bh1 = bh[2 * j + 1];
                    uint32_t bl0 = bl[2 * j], bl1 = bl[2 * j + 1];
#pragma unroll
                    for (int mt = 0; mt < 2; mt++) {
                        MMA_BF16(d[mt][nt], ah[mt][0], ah[mt][1], ah[mt][2], ah[mt][3], bh0, bh1);
                        MMA_BF16(d[mt][nt], ah[mt][0], ah[mt][1], ah[mt][2], ah[mt][3], bl0, bl1);
                        MMA_BF16(d[mt][nt], al[mt][0], al[mt][1], al[mt][2], al[mt][3], bh0, bh1);
                    }
                }
            }
        }

        if (c < 7) {
            __nv_bfloat16* Xhn = (__nv_bfloat16*)(bn + XH_OFF);
            __nv_bfloat16* Xln = (__nv_bfloat16*)(bn + XL_OFF);
#pragma unroll
            for (int i = 0; i < 4; i++) {
                float4 v = xs[i];
                __nv_bfloat162 h01 = make_bfloat162(__float2bfloat16(v.x), __float2bfloat16(v.y));
                __nv_bfloat162 h23 = make_bfloat162(__float2bfloat16(v.z), __float2bfloat16(v.w));
                __nv_bfloat162 l01 = make_bfloat162(
                    __float2bfloat16(v.x - __bfloat162float(h01.x)),
                    __float2bfloat16(v.y - __bfloat162float(h01.y)));
                __nv_bfloat162 l23 = make_bfloat162(
                    __float2bfloat16(v.z - __bfloat162float(h23.x)),
                    __float2bfloat16(v.w - __bfloat162float(h23.y)));
                int o = xrow[i] * 40 + xq[i] * 4;
                *(__nv_bfloat162*)&Xhn[o]     = h01;
                *(__nv_bfloat162*)&Xhn[o + 2] = h23;
                *(__nv_bfloat162*)&Xln[o]     = l01;
                *(__nv_bfloat162*)&Xln[o + 2] = l23;
            }
            CP_WAIT0();
        }
        __syncthreads();
    }

    // ---- epilogue: store h (fp16) + attention logits (fp32) ----
    const int head0 = wn >> 5;
    float psl[2][2], pdl[2][2], psh[2][2], pdh[2][2];
#pragma unroll
    for (int mt = 0; mt < 2; mt++)
#pragma unroll
        for (int hh = 0; hh < 2; hh++) { psl[mt][hh]=pdl[mt][hh]=psh[mt][hh]=pdh[mt][hh]=0.f; }

#pragma unroll
    for (int nt = 0; nt < 8; nt++) {
        int c0 = wn + nt * 8 + 2 * tig;
        int hh = nt >> 2;
        float as0 = __ldg(att_src + c0), as1 = __ldg(att_src + c0 + 1);
        float ad0 = __ldg(att_dst + c0), ad1 = __ldg(att_dst + c0 + 1);
#pragma unroll
        for (int mt = 0; mt < 2; mt++) {
            psl[mt][hh] += d[mt][nt][0] * as0 + d[mt][nt][1] * as1;
            pdl[mt][hh] += d[mt][nt][0] * ad0 + d[mt][nt][1] * ad1;
            psh[mt][hh] += d[mt][nt][2] * as0 + d[mt][nt][3] * as1;
            pdh[mt][hh] += d[mt][nt][2] * ad0 + d[mt][nt][3] * ad1;
        }
    }
#pragma unroll
    for (int mt = 0; mt < 2; mt++)
#pragma unroll
        for (int hh = 0; hh < 2; hh++)
#pragma unroll
            for (int o = 1; o <= 2; o <<= 1) {
                psl[mt][hh] += __shfl_xor_sync(0xffffffffu, psl[mt][hh], o);
                pdl[mt][hh] += __shfl_xor_sync(0xffffffffu, pdl[mt][hh], o);
                psh[mt][hh] += __shfl_xor_sync(0xffffffffu, psh[mt][hh], o);
                pdh[mt][hh] += __shfl_xor_sync(0xffffffffu, pdh[mt][hh], o);
            }

#pragma unroll
    for (int mt = 0; mt < 2; mt++) {
        int n0 = nb + wm + mt * 16 + g;
        int n1 = n0 + 8;
        if (n0 < N_NODES) {
#pragma unroll
            for (int nt = 0; nt < 8; nt++)
                *(__half2*)(g_hf + (size_t)n0 * HC + wn + nt * 8 + 2 * tig) =
                    __floats2half2_rn(d[mt][nt][0], d[mt][nt][1]);
            if (tig == 0)
#pragma unroll
                for (int hh = 0; hh < 2; hh++) {
                    g_as[n0 * HEADS + head0 + hh] = psl[mt][hh];
                    g_ad[n0 * HEADS + head0 + hh] = pdl[mt][hh];
                }
        }
        if (n1 < N_NODES) {
#pragma unroll
            for (int nt = 0; nt < 8; nt++)
                *(__half2*)(g_hf + (size_t)n1 * HC + wn + nt * 8 + 2 * tig) =
                    __floats2half2_rn(d[mt][nt][2], d[mt][nt][3]);
            if (tig == 0)
#pragma unroll
                for (int hh = 0; hh < 2; hh++) {
                    g_as[n1 * HEADS + head0 + hh] = psh[mt][hh];
                    g_ad[n1 * HEADS + head0 + hh] = pdh[mt][hh];
                }
        }
    }
}

// ---------------------------------------------------------------------------
// CSR build: hist -> scan (2-level, warp-shuffle) -> fill
// ---------------------------------------------------------------------------
__global__ __launch_bounds__(256) void hist_k(const int* __restrict__ ei) {
    int e = blockIdx.x * 256 + threadIdx.x;
    if (e < N_EDGES) atomicAdd(&g_deg[__ldg(ei + N_EDGES + e)], 1);
}

__global__ __launch_bounds__(1024) void scan1_k() {
    __shared__ int wsum[32];
    int tid = threadIdx.x, lane = tid & 31, wid = tid >> 5;
    int i = blockIdx.x * 1024 + tid;
    int v = (i < N_NODES) ? g_deg[i] : 0;
    int s = v;
#pragma unroll
    for (int o = 1; o < 32; o <<= 1) {
        int t = __shfl_up_sync(0xffffffffu, s, o);
        if (lane >= o) s += t;
    }
    if (lane == 31) wsum[wid] = s;
    __syncthreads();
    if (wid == 0) {
        int t = wsum[lane];
#pragma unroll
        for (int o = 1; o < 32; o <<= 1) {
            int u = __shfl_up_sync(0xffffffffu, t, o);
            if (lane >= o) t += u;
        }
        wsum[lane] = t;
    }
    __syncthreads();
    if (wid > 0) s += wsum[wid - 1];
    g_scan[i] = s;
    if (tid == 1023) g_poff[blockIdx.x] = s;
}

__global__ __launch_bounds__(64) void scan2_k(int nblk) {
    __shared__ int s[64];
    int tid = threadIdx.x;
    s[tid] = (tid < nblk) ? g_poff[tid] : 0;
    __syncthreads();
    if (tid == 0) {
        int run = 0;
        for (int b = 0; b < nblk; b++) { int t = s[b]; s[b] = run; run += t; }
    }
    __syncthreads();
    if (tid < nblk) g_poff[tid] = s[tid];
}

__global__ __launch_bounds__(256) void scan3_k() {
    int i = blockIdx.x * 256 + threadIdx.x;
    if (i < N_NODES) g_row[i + 1] = g_scan[i] + g_poff[i >> 10];
    if (i == 0) g_row[0] = 0;
}

__global__ __launch_bounds__(256) void fill_k(const int* __restrict__ ei) {
    int e = blockIdx.x * 256 + threadIdx.x;
    if (e >= N_EDGES) return;
    int s = __ldg(ei + e);
    int d = __ldg(ei + N_EDGES + e);
    int pos = g_row[d] + atomicAdd(&g_cur[d], 1);
    g_col[pos] = s;
}

// ---------------------------------------------------------------------------
// Aggregation (fp16 gather, 8-way MLP unroll) fused with LayerNorm + ELU.
// One warp per dst node; lane owns 4 channels (one uint2 = 2 half2).
// ---------------------------------------------------------------------------
__global__ __launch_bounds__(256) void aggr_k(const float* __restrict__ bias,
                                              const float* __restrict__ gamma,
                                              const float* __restrict__ beta,
                                              float* __restrict__ out) {
    int gt   = blockIdx.x * 256 + threadIdx.x;
    int n    = gt >> 5;
    int lane = gt & 31;
    if (n >= N_NODES) return;
    int head = lane >> 3;

    float ad_n = __ldg(g_ad + n * HEADS + head);

    // self-loop initializes the accumulator
    float as_s = __ldg(g_as + n * HEADS + head);
    float z    = as_s + ad_n;
    float w    = __expf(z > 0.f ? z : NEG_SLOPE * z);
    uint2 u0i  = __ldg((const uint2*)(g_hf + (size_t)n * HC) + lane);
    float2 f01 = __half22float2(*(__half2*)&u0i.x);
    float2 f23 = __half22float2(*(__half2*)&u0i.y);
    float a0 = w * f01.x, a1 = w * f01.y, a2 = w * f23.x, a3 = w * f23.y;
    float den = w;

    const int e0 = __ldg(g_row + n), e1 = __ldg(g_row + n + 1);
    int i = e0;

    // --- unrolled by 8: batch independent loads to raise MLP ---
#pragma unroll 1
    for (; i + 8 <= e1; i += 8) {
        int sx[8];
        uint2 ux[8];
        float asx[8];
#pragma unroll
        for (int j = 0; j < 8; j++) sx[j] = __ldg(g_col + i + j);
#pragma unroll
        for (int j = 0; j < 8; j++)
            ux[j] = __ldg((const uint2*)(g_hf + (size_t)sx[j] * HC) + lane);
#pragma unroll
        for (int j = 0; j < 8; j++) asx[j] = __ldg(g_as + sx[j] * HEADS + head);

#pragma unroll
        for (int j = 0; j < 8; j++) {
            float zz = asx[j] + ad_n;
            float ww = __expf(zz > 0.f ? zz : NEG_SLOPE * zz);
            den += ww;
            float2 p  = __half22float2(*(__half2*)&ux[j].x);
            float2 q2 = __half22float2(*(__half2*)&ux[j].y);
            a0 = fmaf(ww, p.x, a0);  a1 = fmaf(ww, p.y, a1);
            a2 = fmaf(ww, q2.x, a2); a3 = fmaf(ww, q2.y, a3);
        }
    }
    // --- tail ---
#pragma unroll 1
    for (; i < e1; i++) {
        int s = __ldg(g_col + i);
        uint2 u  = __ldg((const uint2*)(g_hf + (size_t)s * HC) + lane);
        float as = __ldg(g_as + s * HEADS + head);
        float zz = as + ad_n;
        float ww = __expf(zz > 0.f ? zz : NEG_SLOPE * zz);
        float2 h01 = __half22float2(*(__half2*)&u.x);
        float2 h23 = __half22float2(*(__half2*)&u.y);
        a0 = fmaf(ww, h01.x, a0);
        a1 = fmaf(ww, h01.y, a1);
        a2 = fmaf(ww, h23.x, a2);
        a3 = fmaf(ww, h23.y, a3);
        den += ww;
    }

    float inv = 1.0f / den;
    float4 b4 = __ldg((const float4*)bias + lane);
    float v0 = a0 * inv + b4.x;
    float v1 = a1 * inv + b4.y;
    float v2 = a2 * inv + b4.z;
    float v3 = a3 * inv + b4.w;

    float s = v0 + v1 + v2 + v3;
#pragma unroll
    for (int o = 16; o >= 1; o >>= 1) s += __shfl_xor_sync(0xffffffffu, s, o);
    float mean = s * (1.0f / 128.0f);

    float d0 = v0 - mean, d1 = v1 - mean, d2 = v2 - mean, d3 = v3 - mean;
    float q = d0 * d0 + d1 * d1 + d2 * d2 + d3 * d3;
#pragma unroll
    for (int o = 16; o >= 1; o >>= 1) q += __shfl_xor_sync(0xffffffffu, q, o);
    float r = rsqrtf(q * (1.0f / 128.0f) + LN_EPS);

    float4 g4  = __ldg((const float4*)gamma + lane);
    float4 be4 = __ldg((const float4*)beta + lane);
    float o0 = d0 * r * g4.x + be4.x;
    float o1 = d1 * r * g4.y + be4.y;
    float o2 = d2 * r * g4.z + be4.z;
    float o3 = d3 * r * g4.w + be4.w;
    o0 = o0 > 0.f ? o0 : (expf(o0) - 1.0f);
    o1 = o1 > 0.f ? o1 : (expf(o1) - 1.0f);
    o2 = o2 > 0.f ? o2 : (expf(o2) - 1.0f);
    o3 = o3 > 0.f ? o3 : (expf(o3) - 1.0f);

    *(float4*)(out + (size_t)n * HC + lane * 4) = make_float4(o0, o1, o2, o3);
}

// ---------------------------------------------------------------------------
// Launch: fork the capture stream so the CSR build (edge_index only) runs
// concurrently with prep+gemm (x, W only); join before aggr.
// Stream/events are created ONCE (first call = correctness run, outside
// capture) and reused — no per-call driver allocations, so the harness's
// post-teardown memory baseline is preserved.
// ---------------------------------------------------------------------------
extern "C" void kernel_launch(void* const* d_in, const int* in_sizes, int n_in,
                              void* d_out, int out_size) {
    const float* x       = (const float*)d_in[0];
    const int*   ei      = (const int*)d_in[1];
    const float* W       = (const float*)d_in[2];
    const float* att_src = (const float*)d_in[3];
    const float* att_dst = (const float*)d_in[4];
    const float* bias    = (const float*)d_in[5];
    const float* gamma   = (const float*)d_in[6];
    const float* beta    = (const float*)d_in[7];
    float*       out     = (float*)d_out;

    const int NB_SCAN1  = (N_NODES + 1023) / 1024;  // 49
    const int GEMM_SMEM = 2 * STG_BYTES;            // 80 KB dynamic

    static bool init_done = false;
    static cudaStream_t s2;
    static cudaEvent_t ev_fork, ev_join;
    if (!init_done) {
        cudaFuncSetAttribute(gemm_mma_k,
                             cudaFuncAttributeMaxDynamicSharedMemorySize, GEMM_SMEM);
        cudaStreamCreateWithFlags(&s2, cudaStreamNonBlocking);
        cudaEventCreateWithFlags(&ev_fork, cudaEventDisableTiming);
        cudaEventCreateWithFlags(&ev_join, cudaEventDisableTiming);
        init_done = true;
    }

    cudaEventRecord(ev_fork, 0);
    cudaStreamWaitEvent(s2, ev_fork, 0);

    // --- branch A (stream 0): W prep + GEMM/logits ---
    prep_k<<<(IN_DIM * HC + 255) / 256, 256>>>(W);
    gemm_mma_k<<<(N_NODES + 127) / 128, 256, GEMM_SMEM>>>(x, att_src, att_dst);

    // --- branch B (s2): CSR build ---
    zero_k<<<(N_NODES + 255) / 256, 256, 0, s2>>>();
    hist_k<<<(N_EDGES + 255) / 256, 256, 0, s2>>>(ei);
    scan1_k<<<NB_SCAN1, 1024, 0, s2>>>();
    scan2_k<<<1, 64, 0, s2>>>(NB_SCAN1);
    scan3_k<<<(N_NODES + 255) / 256, 256, 0, s2>>>();
    fill_k<<<(N_EDGES + 255) / 256, 256, 0, s2>>>(ei);
    cudaEventRecord(ev_join, s2);

    // --- join, then aggregation + LN + ELU ---
    cudaStreamWaitEvent(0, ev_join, 0);
    aggr_k<<<(N_NODES * 32 + 255) / 256, 256>>>(bias, gamma, beta, out);
}